// round 8
// baseline (speedup 1.0000x reference)
#include <cuda_runtime.h>
#include <float.h>
#include <math.h>

// Problem constants (fixed by reference setup_inputs)
#define BB 8
#define SS 4096
#define CC 1024
#define HH 64
#define NS 128          // S splits for partial reduction
#define SROWS (SS/NS)   // 32 rows per partial chunk

// Scratch (no allocations allowed in kernel_launch)
__device__ float g_psum[BB*NS*CC];
__device__ float g_pmax[BB*NS*CC];
__device__ int   g_pcnt[BB*NS];
__device__ float g_sum [BB*CC];
__device__ float g_max [BB*CC];
__device__ float g_a   [BB*CC];

#define ACC(v)  do { \
    sum.x += (v).x; sum.y += (v).y; sum.z += (v).z; sum.w += (v).w; \
    mx.x = fmaxf(mx.x, (v).x); mx.y = fmaxf(mx.y, (v).y);           \
    mx.z = fmaxf(mx.z, (v).z); mx.w = fmaxf(mx.w, (v).w); } while (0)

#define ACCSM(s, m) do { \
    sum.x += (s).x; sum.y += (s).y; sum.z += (s).z; sum.w += (s).w; \
    mx.x = fmaxf(mx.x, (m).x); mx.y = fmaxf(mx.y, (m).y);           \
    mx.z = fmaxf(mx.z, (m).z); mx.w = fmaxf(mx.w, (m).w); } while (0)

// ---------------------------------------------------------------------------
// Kernel 1: partial masked sum/max over a 32-row chunk, full 1024 channels.
// Warp-ballot compaction of valid rows -> branch-free loop, 8 rows in flight.
// grid (NS, BB) = 1024 blocks, 256 threads.
// ---------------------------------------------------------------------------
__global__ void k_partial(const float* __restrict__ x,
                          const int*   __restrict__ mask) {
    const int ns = blockIdx.x;
    const int b  = blockIdx.y;
    const int c4 = threadIdx.x;              // float4 index 0..255

    __shared__ int srows[SROWS];
    __shared__ int snv;
    const int s0 = ns * SROWS;

    if (threadIdx.x < 32) {
        const int lane = threadIdx.x;
        const int m = mask[b * SS + s0 + lane];
        const unsigned bal = __ballot_sync(0xFFFFFFFFu, m != 0);
        if (m) srows[__popc(bal & ((1u << lane) - 1u))] = lane;
        if (lane == 0) {
            snv = __popc(bal);
            g_pcnt[b * NS + ns] = __popc(bal);
        }
    }
    __syncthreads();
    const int nv = snv;

    float4 sum = make_float4(0.f, 0.f, 0.f, 0.f);
    float4 mx  = make_float4(-FLT_MAX, -FLT_MAX, -FLT_MAX, -FLT_MAX);

    const float4* xp = reinterpret_cast<const float4*>(
        x + ((size_t)b * SS + s0) * CC) + c4;

    int i = 0;
    for (; i + 8 <= nv; i += 8) {
        const int r0 = srows[i + 0], r1 = srows[i + 1];
        const int r2 = srows[i + 2], r3 = srows[i + 3];
        const int r4 = srows[i + 4], r5 = srows[i + 5];
        const int r6 = srows[i + 6], r7 = srows[i + 7];
        float4 v0 = __ldcs(xp + (size_t)r0 * (CC / 4));
        float4 v1 = __ldcs(xp + (size_t)r1 * (CC / 4));
        float4 v2 = __ldcs(xp + (size_t)r2 * (CC / 4));
        float4 v3 = __ldcs(xp + (size_t)r3 * (CC / 4));
        float4 v4 = __ldcs(xp + (size_t)r4 * (CC / 4));
        float4 v5 = __ldcs(xp + (size_t)r5 * (CC / 4));
        float4 v6 = __ldcs(xp + (size_t)r6 * (CC / 4));
        float4 v7 = __ldcs(xp + (size_t)r7 * (CC / 4));
        ACC(v0); ACC(v1); ACC(v2); ACC(v3);
        ACC(v4); ACC(v5); ACC(v6); ACC(v7);
    }
    if (i + 4 <= nv) {
        const int r0 = srows[i + 0], r1 = srows[i + 1];
        const int r2 = srows[i + 2], r3 = srows[i + 3];
        float4 v0 = __ldcs(xp + (size_t)r0 * (CC / 4));
        float4 v1 = __ldcs(xp + (size_t)r1 * (CC / 4));
        float4 v2 = __ldcs(xp + (size_t)r2 * (CC / 4));
        float4 v3 = __ldcs(xp + (size_t)r3 * (CC / 4));
        ACC(v0); ACC(v1); ACC(v2); ACC(v3);
        i += 4;
    }
    for (; i < nv; i++) {
        float4 v0 = __ldcs(xp + (size_t)srows[i] * (CC / 4));
        ACC(v0);
    }

    reinterpret_cast<float4*>(g_psum + (b * NS + ns) * CC)[c4] = sum;
    reinterpret_cast<float4*>(g_pmax + (b * NS + ns) * CC)[c4] = mx;
}

// ---------------------------------------------------------------------------
// Kernel 2: fold NS=128 partials -> g_sum/g_max.
// grid (CC/4/32 = 8, BB) = 64 blocks, 256 threads = 8 slices x 32 groups.
// ---------------------------------------------------------------------------
__global__ void k_fold() {
    const int b  = blockIdx.y;
    const int g  = threadIdx.x & 31;         // channel group in block
    const int sl = threadIdx.x >> 5;         // 0..7 ns slice
    const int c4 = blockIdx.x * 32 + g;      // global float4 group

    __shared__ float4 ssum[8][32];
    __shared__ float4 smax[8][32];

    float4 sum = make_float4(0.f, 0.f, 0.f, 0.f);
    float4 mx  = make_float4(-FLT_MAX, -FLT_MAX, -FLT_MAX, -FLT_MAX);
    const float4* ps = reinterpret_cast<const float4*>(
        g_psum + (b * NS + sl * 16) * CC) + c4;
    const float4* pm = reinterpret_cast<const float4*>(
        g_pmax + (b * NS + sl * 16) * CC) + c4;
    #pragma unroll
    for (int k = 0; k < 16; k++) {
        float4 s = ps[(size_t)k * (CC / 4)];
        float4 m = pm[(size_t)k * (CC / 4)];
        ACCSM(s, m);
    }
    ssum[sl][g] = sum;
    smax[sl][g] = mx;
    __syncthreads();

    if (sl == 0) {
        #pragma unroll
        for (int k = 1; k < 8; k++) {
            float4 s = ssum[k][g];
            float4 m = smax[k][g];
            ACCSM(s, m);
        }
        reinterpret_cast<float4*>(g_sum + b * CC)[c4] = sum;
        reinterpret_cast<float4*>(g_max + b * CC)[c4] = mx;
    }
}

// ---------------------------------------------------------------------------
// Kernel 3: MLP. grid = BB, 1024 threads.
// ---------------------------------------------------------------------------
__global__ void __launch_bounds__(1024)
k_mlp(const float* __restrict__ W0,     // [H, C]
      const float* __restrict__ W1) {   // [C, H]
    const int b = blockIdx.x;
    const int tid  = threadIdx.x;
    const int warp = tid >> 5;
    const int lane = tid & 31;

    __shared__ float smean[CC];
    __shared__ float smax [CC];
    __shared__ float hsum [HH];
    __shared__ float scount;

    float4 S = make_float4(0.f, 0.f, 0.f, 0.f);
    float4 M = S;
    if (tid < 256) {
        S = reinterpret_cast<const float4*>(g_sum + b * CC)[tid];
        M = reinterpret_cast<const float4*>(g_max + b * CC)[tid];
    }
    if (warp == 0) {
        const int* pc = g_pcnt + b * NS;
        int c = pc[lane] + pc[lane + 32] + pc[lane + 64] + pc[lane + 96];
        #pragma unroll
        for (int off = 16; off > 0; off >>= 1)
            c += __shfl_xor_sync(0xFFFFFFFFu, c, off);
        if (lane == 0) scount = fmaxf((float)c, 1.0f);
    }
    __syncthreads();
    if (tid < 256) {
        const float inv = 1.0f / scount;
        S.x *= inv; S.y *= inv; S.z *= inv; S.w *= inv;
        reinterpret_cast<float4*>(smean)[tid] = S;
        reinterpret_cast<float4*>(smax )[tid] = M;
    }
    __syncthreads();

    #pragma unroll
    for (int jj = 0; jj < 2; jj++) {
        const int j = warp + jj * 32;
        const float* w = W0 + j * CC;
        float dm = 0.0f, dx = 0.0f;
        #pragma unroll 8
        for (int k = lane; k < CC; k += 32) {
            float wv = w[k];
            dm += wv * smean[k];
            dx += wv * smax[k];
        }
        #pragma unroll
        for (int off = 16; off > 0; off >>= 1) {
            dm += __shfl_xor_sync(0xFFFFFFFFu, dm, off);
            dx += __shfl_xor_sync(0xFFFFFFFFu, dx, off);
        }
        if (lane == 0)
            hsum[j] = fmaxf(dm, 0.0f) + fmaxf(dx, 0.0f);
    }
    __syncthreads();

    {
        const float4* w1 = reinterpret_cast<const float4*>(W1 + tid * HH);
        float acc = 0.0f;
        #pragma unroll
        for (int j = 0; j < HH / 4; j++) {
            float4 w = w1[j];
            acc += w.x * hsum[j * 4 + 0] + w.y * hsum[j * 4 + 1]
                 + w.z * hsum[j * 4 + 2] + w.w * hsum[j * 4 + 3];
        }
        g_a[b * CC + tid] = 1.0f / (1.0f + expf(-acc));
    }
}

// ---------------------------------------------------------------------------
// Kernel 4: out[b,s,c] = x[b,s,c] * a[b,c]   (float4 streaming, .cs hints)
// ---------------------------------------------------------------------------
__global__ void k_scale(const float* __restrict__ x,
                        float*       __restrict__ out) {
    const int b = blockIdx.y;
    const unsigned i = blockIdx.x * blockDim.x + threadIdx.x;  // float4 idx
    const unsigned c4 = i & (CC / 4 - 1);                       // 0..255

    const size_t gi = (size_t)b * (SS * CC / 4) + i;
    float4 v = __ldcs(reinterpret_cast<const float4*>(x) + gi);
    float4 a = reinterpret_cast<const float4*>(g_a + b * CC)[c4];
    v.x *= a.x; v.y *= a.y; v.z *= a.z; v.w *= a.w;
    __stcs(reinterpret_cast<float4*>(out) + gi, v);
}

// ---------------------------------------------------------------------------
extern "C" void kernel_launch(void* const* d_in, const int* in_sizes, int n_in,
                              void* d_out, int out_size) {
    const float* x    = (const float*)d_in[0];   // [B,S,C]
    const int*   mask = (const int*)  d_in[1];   // [B,S]
    const float* W0   = (const float*)d_in[2];   // [H,C]
    const float* W1   = (const float*)d_in[3];   // [C,H]
    float*       out  = (float*)d_out;           // [B,S,C]

    (void)in_sizes; (void)n_in; (void)out_size;

    {   dim3 grid(NS, BB);                  k_partial<<<grid, 256>>>(x, mask); }
    {   dim3 grid(CC / 4 / 32, BB);         k_fold   <<<grid, 256>>>();        }
    {   k_mlp<<<BB, 1024>>>(W0, W1); }
    {   dim3 grid((SS * CC / 4) / 256, BB); k_scale  <<<grid, 256>>>(x, out);  }
}

// round 9
// speedup vs baseline: 1.1205x; 1.1205x over previous
#include <cuda_runtime.h>
#include <float.h>
#include <math.h>

// Problem constants (fixed by reference setup_inputs)
#define BB 8
#define SS 4096
#define CC 1024
#define HH 64
#define NS 128          // S splits for partial reduction
#define SROWS (SS/NS)   // 32 rows per partial chunk

// Scratch (no allocations allowed in kernel_launch)
__device__ float g_psum[BB*NS*CC];
__device__ float g_pmax[BB*NS*CC];
__device__ int   g_pcnt[BB*NS];
__device__ float g_mean[BB*CC];
__device__ float g_max [BB*CC];
__device__ float g_hsum[BB*HH];
__device__ float g_a   [BB*CC];

#define ACC(v)  do { \
    sum.x += (v).x; sum.y += (v).y; sum.z += (v).z; sum.w += (v).w; \
    mx.x = fmaxf(mx.x, (v).x); mx.y = fmaxf(mx.y, (v).y);           \
    mx.z = fmaxf(mx.z, (v).z); mx.w = fmaxf(mx.w, (v).w); } while (0)

#define ACCSM(s, m) do { \
    sum.x += (s).x; sum.y += (s).y; sum.z += (s).z; sum.w += (s).w; \
    mx.x = fmaxf(mx.x, (m).x); mx.y = fmaxf(mx.y, (m).y);           \
    mx.z = fmaxf(mx.z, (m).z); mx.w = fmaxf(mx.w, (m).w); } while (0)

// ---------------------------------------------------------------------------
// Kernel 1: partial masked sum/max over a 32-row chunk, full 1024 channels.
// Warp-ballot compaction of valid rows -> branch-free loop, 4 rows/iter.
// grid (NS, BB) = 1024 blocks, 256 threads.  (R7-measured: 17.0 us)
// ---------------------------------------------------------------------------
__global__ void k_partial(const float* __restrict__ x,
                          const int*   __restrict__ mask) {
    const int ns = blockIdx.x;
    const int b  = blockIdx.y;
    const int c4 = threadIdx.x;              // float4 index 0..255

    __shared__ int srows[SROWS];
    __shared__ int snv;
    const int s0 = ns * SROWS;

    if (threadIdx.x < 32) {
        const int lane = threadIdx.x;
        const int m = mask[b * SS + s0 + lane];
        const unsigned bal = __ballot_sync(0xFFFFFFFFu, m != 0);
        if (m) srows[__popc(bal & ((1u << lane) - 1u))] = lane;
        if (lane == 0) {
            snv = __popc(bal);
            g_pcnt[b * NS + ns] = __popc(bal);
        }
    }
    __syncthreads();
    const int nv = snv;

    float4 sum = make_float4(0.f, 0.f, 0.f, 0.f);
    float4 mx  = make_float4(-FLT_MAX, -FLT_MAX, -FLT_MAX, -FLT_MAX);

    const float4* xp = reinterpret_cast<const float4*>(
        x + ((size_t)b * SS + s0) * CC) + c4;

    int i = 0;
    for (; i + 4 <= nv; i += 4) {
        const int r0 = srows[i];
        const int r1 = srows[i + 1];
        const int r2 = srows[i + 2];
        const int r3 = srows[i + 3];
        float4 v0 = xp[(size_t)r0 * (CC / 4)];
        float4 v1 = xp[(size_t)r1 * (CC / 4)];
        float4 v2 = xp[(size_t)r2 * (CC / 4)];
        float4 v3 = xp[(size_t)r3 * (CC / 4)];
        ACC(v0); ACC(v1); ACC(v2); ACC(v3);
    }
    for (; i < nv; i++) {
        float4 v0 = xp[(size_t)srows[i] * (CC / 4)];
        ACC(v0);
    }

    reinterpret_cast<float4*>(g_psum + (b * NS + ns) * CC)[c4] = sum;
    reinterpret_cast<float4*>(g_pmax + (b * NS + ns) * CC)[c4] = mx;
}

// ---------------------------------------------------------------------------
// Kernel 2: fold NS=128 partials -> g_mean/g_max.
// grid (8, BB) = 64 blocks, 256 threads = 8 slices x 32 float4 groups.
// ---------------------------------------------------------------------------
__global__ void k_finalize() {
    const int b  = blockIdx.y;
    const int g  = threadIdx.x & 31;         // channel group in block
    const int sl = threadIdx.x >> 5;         // 0..7 ns slice
    const int c4 = blockIdx.x * 32 + g;      // global float4 group

    __shared__ float4 ssum[8][32];
    __shared__ float4 smax[8][32];
    __shared__ float  scount;

    float4 sum = make_float4(0.f, 0.f, 0.f, 0.f);
    float4 mx  = make_float4(-FLT_MAX, -FLT_MAX, -FLT_MAX, -FLT_MAX);
    const float4* ps = reinterpret_cast<const float4*>(
        g_psum + (b * NS + sl * 16) * CC) + c4;
    const float4* pm = reinterpret_cast<const float4*>(
        g_pmax + (b * NS + sl * 16) * CC) + c4;
    #pragma unroll
    for (int k = 0; k < 16; k++) {
        float4 s = ps[(size_t)k * (CC / 4)];
        float4 m = pm[(size_t)k * (CC / 4)];
        ACCSM(s, m);
    }
    ssum[sl][g] = sum;
    smax[sl][g] = mx;

    // count reduction in warp 0 (racing with the stores above is fine: ballot
    // warp only reads g_pcnt)
    if (threadIdx.x < 32) {
        const int lane = threadIdx.x;
        const int* pc = g_pcnt + b * NS;
        int c = pc[lane] + pc[lane + 32] + pc[lane + 64] + pc[lane + 96];
        #pragma unroll
        for (int off = 16; off > 0; off >>= 1)
            c += __shfl_xor_sync(0xFFFFFFFFu, c, off);
        if (lane == 0) scount = fmaxf((float)c, 1.0f);
    }
    __syncthreads();

    if (sl == 0) {
        #pragma unroll
        for (int k = 1; k < 8; k++) {
            float4 s = ssum[k][g];
            float4 m = smax[k][g];
            ACCSM(s, m);
        }
        const float inv = 1.0f / scount;
        sum.x *= inv; sum.y *= inv; sum.z *= inv; sum.w *= inv;
        reinterpret_cast<float4*>(g_mean + b * CC)[c4] = sum;
        reinterpret_cast<float4*>(g_max  + b * CC)[c4] = mx;
    }
}

// ---------------------------------------------------------------------------
// Kernel 3a: hsum[b,j] = relu(mean[b].W0[j]) + relu(max[b].W0[j])
// grid (HH/8 = 8, BB), 256 threads = 8 warps, one warp per hidden unit.
// ---------------------------------------------------------------------------
__global__ void k_mlp1(const float* __restrict__ W0) {   // [H, C]
    const int b = blockIdx.y;
    const int warp = threadIdx.x >> 5;
    const int lane = threadIdx.x & 31;
    const int j = blockIdx.x * 8 + warp;

    __shared__ float smean[CC];
    __shared__ float smax [CC];
    for (int i = threadIdx.x; i < CC; i += blockDim.x) {
        smean[i] = g_mean[b * CC + i];
        smax [i] = g_max [b * CC + i];
    }
    __syncthreads();

    const float* w = W0 + j * CC;
    float dm = 0.0f, dx = 0.0f;
    #pragma unroll 8
    for (int k = lane; k < CC; k += 32) {
        float wv = w[k];
        dm += wv * smean[k];
        dx += wv * smax[k];
    }
    #pragma unroll
    for (int off = 16; off > 0; off >>= 1) {
        dm += __shfl_xor_sync(0xFFFFFFFFu, dm, off);
        dx += __shfl_xor_sync(0xFFFFFFFFu, dx, off);
    }
    if (lane == 0)
        g_hsum[b * HH + j] = fmaxf(dm, 0.0f) + fmaxf(dx, 0.0f);
}

// ---------------------------------------------------------------------------
// Kernel 3b: a[b,c] = sigmoid(W1[c].hsum[b]).  grid (CC/256 = 4, BB), 256 thr.
// ---------------------------------------------------------------------------
__global__ void k_mlp2(const float* __restrict__ W1) {   // [C, H]
    const int b = blockIdx.y;
    const int c = blockIdx.x * blockDim.x + threadIdx.x;

    __shared__ float sh[HH];
    if (threadIdx.x < HH) sh[threadIdx.x] = g_hsum[b * HH + threadIdx.x];
    __syncthreads();

    const float4* w1 = reinterpret_cast<const float4*>(W1 + c * HH);
    float acc = 0.0f;
    #pragma unroll
    for (int j = 0; j < HH / 4; j++) {
        float4 w = w1[j];
        acc += w.x * sh[j * 4 + 0] + w.y * sh[j * 4 + 1]
             + w.z * sh[j * 4 + 2] + w.w * sh[j * 4 + 3];
    }
    g_a[b * CC + c] = 1.0f / (1.0f + expf(-acc));
}

// ---------------------------------------------------------------------------
// Kernel 4: out[b,s,c] = x[b,s,c] * a[b,c]
// 2 consecutive float4 per thread (32 B). grid ((S*C/8)/256, B), 256 thr.
// ---------------------------------------------------------------------------
__global__ void k_scale(const float* __restrict__ x,
                        float*       __restrict__ out) {
    const int b = blockIdx.y;
    const unsigned t = blockIdx.x * blockDim.x + threadIdx.x;  // pair index
    const unsigned i0 = t * 2;                                  // float4 idx
    const unsigned c40 = i0 & (CC / 4 - 1);
    const unsigned c41 = (i0 + 1) & (CC / 4 - 1);

    const size_t gi = (size_t)b * (SS * CC / 4) + i0;
    float4 v0 = __ldcs(reinterpret_cast<const float4*>(x) + gi);
    float4 v1 = __ldcs(reinterpret_cast<const float4*>(x) + gi + 1);
    float4 a0 = reinterpret_cast<const float4*>(g_a + b * CC)[c40];
    float4 a1 = reinterpret_cast<const float4*>(g_a + b * CC)[c41];
    v0.x *= a0.x; v0.y *= a0.y; v0.z *= a0.z; v0.w *= a0.w;
    v1.x *= a1.x; v1.y *= a1.y; v1.z *= a1.z; v1.w *= a1.w;
    __stcs(reinterpret_cast<float4*>(out) + gi,     v0);
    __stcs(reinterpret_cast<float4*>(out) + gi + 1, v1);
}

// ---------------------------------------------------------------------------
extern "C" void kernel_launch(void* const* d_in, const int* in_sizes, int n_in,
                              void* d_out, int out_size) {
    const float* x    = (const float*)d_in[0];   // [B,S,C]
    const int*   mask = (const int*)  d_in[1];   // [B,S]
    const float* W0   = (const float*)d_in[2];   // [H,C]
    const float* W1   = (const float*)d_in[3];   // [C,H]
    float*       out  = (float*)d_out;           // [B,S,C]

    (void)in_sizes; (void)n_in; (void)out_size;

    {   dim3 grid(NS, BB);                  k_partial <<<grid, 256>>>(x, mask); }
    {   dim3 grid(CC / 4 / 32, BB);         k_finalize<<<grid, 256>>>();        }
    {   dim3 grid(HH / 8, BB);              k_mlp1    <<<grid, 256>>>(W0);      }
    {   dim3 grid(CC / 256, BB);            k_mlp2    <<<grid, 256>>>(W1);      }
    {   dim3 grid((SS * CC / 8) / 256, BB); k_scale   <<<grid, 256>>>(x, out);  }
}

// round 12
// speedup vs baseline: 1.1964x; 1.0677x over previous
#include <cuda_runtime.h>
#include <float.h>
#include <math.h>

// Problem constants (fixed by reference setup_inputs)
#define BB 8
#define SS 4096
#define CC 1024
#define HH 64
#define NS 128          // S splits for partial reduction
#define SROWS (SS/NS)   // 32 rows per partial chunk

// Scratch (no allocations allowed in kernel_launch)
__device__ float g_psum[BB*NS*CC];
__device__ float g_pmax[BB*NS*CC];
__device__ int   g_pcnt[BB*NS];
__device__ float g_mean[BB*CC];
__device__ float g_max [BB*CC];
__device__ float g_hsum[BB*HH];
__device__ float g_a   [BB*CC];
__device__ unsigned g_bar = 0;   // monotonic grid-barrier ticket counter

#define ACC(v)  do { \
    sum.x += (v).x; sum.y += (v).y; sum.z += (v).z; sum.w += (v).w; \
    mx.x = fmaxf(mx.x, (v).x); mx.y = fmaxf(mx.y, (v).y);           \
    mx.z = fmaxf(mx.z, (v).z); mx.w = fmaxf(mx.w, (v).w); } while (0)

#define ACCSM(s, m) do { \
    sum.x += (s).x; sum.y += (s).y; sum.z += (s).z; sum.w += (s).w; \
    mx.x = fmaxf(mx.x, (m).x); mx.y = fmaxf(mx.y, (m).y);           \
    mx.z = fmaxf(mx.z, (m).z); mx.w = fmaxf(mx.w, (m).w); } while (0)

// Software grid barrier for a co-resident grid of nb blocks.
// Monotonic ticket counter -> safe across graph replays (no reset needed).
__device__ __forceinline__ void gridbar(unsigned nb) {
    __syncthreads();
    __threadfence();
    if (threadIdx.x == 0) {
        const unsigned t = atomicAdd(&g_bar, 1u);
        const unsigned target = (t / nb + 1u) * nb;
        while (*((volatile unsigned*)&g_bar) < target) { }
    }
    __syncthreads();
}

// ---------------------------------------------------------------------------
// Kernel 1: partial masked sum/max over a 32-row chunk, full 1024 channels.
// Warp-ballot compaction of valid rows -> branch-free loop, 4 rows/iter.
// grid (NS, BB) = 1024 blocks, 256 threads.  (measured 17.0 us)
// ---------------------------------------------------------------------------
__global__ void k_partial(const float* __restrict__ x,
                          const int*   __restrict__ mask) {
    const int ns = blockIdx.x;
    const int b  = blockIdx.y;
    const int c4 = threadIdx.x;              // float4 index 0..255

    __shared__ int srows[SROWS];
    __shared__ int snv;
    const int s0 = ns * SROWS;

    if (threadIdx.x < 32) {
        const int lane = threadIdx.x;
        const int m = mask[b * SS + s0 + lane];
        const unsigned bal = __ballot_sync(0xFFFFFFFFu, m != 0);
        if (m) srows[__popc(bal & ((1u << lane) - 1u))] = lane;
        if (lane == 0) {
            snv = __popc(bal);
            g_pcnt[b * NS + ns] = __popc(bal);
        }
    }
    __syncthreads();
    const int nv = snv;

    float4 sum = make_float4(0.f, 0.f, 0.f, 0.f);
    float4 mx  = make_float4(-FLT_MAX, -FLT_MAX, -FLT_MAX, -FLT_MAX);

    const float4* xp = reinterpret_cast<const float4*>(
        x + ((size_t)b * SS + s0) * CC) + c4;

    int i = 0;
    for (; i + 4 <= nv; i += 4) {
        const int r0 = srows[i];
        const int r1 = srows[i + 1];
        const int r2 = srows[i + 2];
        const int r3 = srows[i + 3];
        float4 v0 = xp[(size_t)r0 * (CC / 4)];
        float4 v1 = xp[(size_t)r1 * (CC / 4)];
        float4 v2 = xp[(size_t)r2 * (CC / 4)];
        float4 v3 = xp[(size_t)r3 * (CC / 4)];
        ACC(v0); ACC(v1); ACC(v2); ACC(v3);
    }
    for (; i < nv; i++) {
        float4 v0 = xp[(size_t)srows[i] * (CC / 4)];
        ACC(v0);
    }

    reinterpret_cast<float4*>(g_psum + (b * NS + ns) * CC)[c4] = sum;
    reinterpret_cast<float4*>(g_pmax + (b * NS + ns) * CC)[c4] = mx;
}

// ---------------------------------------------------------------------------
// Kernel 2 (fused tail with grid barriers): fold -> MLP1 -> MLP2.
// grid (8, BB) = 64 blocks (co-resident on 148 SMs), 256 threads.
//   Phase A: block (chunk,b) folds NS partials for 128 channels (8 slices).
//   Phase B: block (chunk,b) computes 8 hidden units (one per warp).
//   Phase C: block (chunk,b) computes a[] for its 128 channels.
// All float4-cast shared arrays are 16B-aligned (the R11 crash was a
// float[] -> float4* cast on 4B-aligned smem).
// ---------------------------------------------------------------------------
#define NBLK (8*BB)

__global__ void __launch_bounds__(256)
k_tail(const float* __restrict__ W0,     // [H, C]
       const float* __restrict__ W1) {   // [C, H]
    const int chunk = blockIdx.x;        // 0..7
    const int b     = blockIdx.y;
    const int tid   = threadIdx.x;
    const int warp  = tid >> 5;
    const int lane  = tid & 31;

    __shared__ float4 ssum[8][32];
    __shared__ float4 smax4[8][32];
    __shared__ __align__(16) float smean[CC];
    __shared__ __align__(16) float smaxv[CC];
    __shared__ __align__(16) float sh[HH];
    __shared__ float  scount;

    // ---- Phase A: fold NS=128 partials for channels [chunk*128, +128) ----
    {
        const int g  = tid & 31;             // float4 group in chunk
        const int sl = tid >> 5;             // ns slice 0..7
        const int c4 = chunk * 32 + g;

        float4 sum = make_float4(0.f, 0.f, 0.f, 0.f);
        float4 mx  = make_float4(-FLT_MAX, -FLT_MAX, -FLT_MAX, -FLT_MAX);
        const float4* ps = reinterpret_cast<const float4*>(
            g_psum + (b * NS + sl * 16) * CC) + c4;
        const float4* pm = reinterpret_cast<const float4*>(
            g_pmax + (b * NS + sl * 16) * CC) + c4;
        #pragma unroll
        for (int k = 0; k < 16; k++) {
            float4 s = ps[(size_t)k * (CC / 4)];
            float4 m = pm[(size_t)k * (CC / 4)];
            ACCSM(s, m);
        }
        ssum[sl][g]  = sum;
        smax4[sl][g] = mx;

        if (tid < 32) {
            const int* pc = g_pcnt + b * NS;
            int c = pc[lane] + pc[lane + 32] + pc[lane + 64] + pc[lane + 96];
            #pragma unroll
            for (int off = 16; off > 0; off >>= 1)
                c += __shfl_xor_sync(0xFFFFFFFFu, c, off);
            if (lane == 0) scount = fmaxf((float)c, 1.0f);
        }
        __syncthreads();

        if (tid < 32) {    // lane g folds the 8 slices
            const int g0 = tid;
            float4 sum2 = ssum[0][g0];
            float4 mx2  = smax4[0][g0];
            #pragma unroll
            for (int k = 1; k < 8; k++) {
                float4 s = ssum[k][g0];
                float4 m = smax4[k][g0];
                sum2.x += s.x; sum2.y += s.y; sum2.z += s.z; sum2.w += s.w;
                mx2.x = fmaxf(mx2.x, m.x); mx2.y = fmaxf(mx2.y, m.y);
                mx2.z = fmaxf(mx2.z, m.z); mx2.w = fmaxf(mx2.w, m.w);
            }
            const float inv = 1.0f / scount;
            sum2.x *= inv; sum2.y *= inv; sum2.z *= inv; sum2.w *= inv;
            reinterpret_cast<float4*>(g_mean + b * CC)[chunk * 32 + g0] = sum2;
            reinterpret_cast<float4*>(g_max  + b * CC)[chunk * 32 + g0] = mx2;
        }
    }

    gridbar(NBLK);

    // ---- Phase B: hidden units j = chunk*8 + warp for batch b -----------
    {
        {
            float4 S = reinterpret_cast<const float4*>(g_mean + b * CC)[tid];
            float4 M = reinterpret_cast<const float4*>(g_max  + b * CC)[tid];
            reinterpret_cast<float4*>(smean)[tid] = S;
            reinterpret_cast<float4*>(smaxv)[tid] = M;
        }
        __syncthreads();

        const int j = chunk * 8 + warp;
        const float* w = W0 + j * CC;
        float dm = 0.0f, dx = 0.0f;
        #pragma unroll 8
        for (int k = lane; k < CC; k += 32) {
            float wv = w[k];
            dm += wv * smean[k];
            dx += wv * smaxv[k];
        }
        #pragma unroll
        for (int off = 16; off > 0; off >>= 1) {
            dm += __shfl_xor_sync(0xFFFFFFFFu, dm, off);
            dx += __shfl_xor_sync(0xFFFFFFFFu, dx, off);
        }
        if (lane == 0)
            g_hsum[b * HH + j] = fmaxf(dm, 0.0f) + fmaxf(dx, 0.0f);
    }

    gridbar(NBLK);

    // ---- Phase C: a[] for channels [chunk*128, +128) --------------------
    {
        if (tid < HH) sh[tid] = g_hsum[b * HH + tid];
        __syncthreads();

        if (tid < 128) {
            const int c = chunk * 128 + tid;
            const float4* w1 = reinterpret_cast<const float4*>(W1 + c * HH);
            float acc = 0.0f;
            #pragma unroll
            for (int j = 0; j < HH / 4; j++) {
                float4 w = w1[j];
                acc += w.x * sh[j * 4 + 0] + w.y * sh[j * 4 + 1]
                     + w.z * sh[j * 4 + 2] + w.w * sh[j * 4 + 3];
            }
            g_a[b * CC + c] = 1.0f / (1.0f + expf(-acc));
        }
    }
}

// ---------------------------------------------------------------------------
// Kernel 3: out[b,s,c] = x[b,s,c] * a[b,c]   (float4 streaming, .cs hints)
// grid ((S*C/4)/256, B)
// ---------------------------------------------------------------------------
__global__ void k_scale(const float* __restrict__ x,
                        float*       __restrict__ out) {
    const int b = blockIdx.y;
    const unsigned i = blockIdx.x * blockDim.x + threadIdx.x;  // float4 idx
    const unsigned c4 = i & (CC / 4 - 1);                       // 0..255

    const size_t gi = (size_t)b * (SS * CC / 4) + i;
    float4 v = __ldcs(reinterpret_cast<const float4*>(x) + gi);
    float4 a = reinterpret_cast<const float4*>(g_a + b * CC)[c4];
    v.x *= a.x; v.y *= a.y; v.z *= a.z; v.w *= a.w;
    __stcs(reinterpret_cast<float4*>(out) + gi, v);
}

// ---------------------------------------------------------------------------
extern "C" void kernel_launch(void* const* d_in, const int* in_sizes, int n_in,
                              void* d_out, int out_size) {
    const float* x    = (const float*)d_in[0];   // [B,S,C]
    const int*   mask = (const int*)  d_in[1];   // [B,S]
    const float* W0   = (const float*)d_in[2];   // [H,C]
    const float* W1   = (const float*)d_in[3];   // [C,H]
    float*       out  = (float*)d_out;           // [B,S,C]

    (void)in_sizes; (void)n_in; (void)out_size;

    {   dim3 grid(NS, BB);                  k_partial<<<grid, 256>>>(x, mask); }
    {   dim3 grid(8, BB);                   k_tail   <<<grid, 256>>>(W0, W1);  }
    {   dim3 grid((SS * CC / 4) / 256, BB); k_scale  <<<grid, 256>>>(x, out);  }
}